// round 11
// baseline (speedup 1.0000x reference)
#include <cuda_runtime.h>
#include <cuda_fp16.h>
#include <cstdint>

// ============================================================
// Problem: out[B,256] = relu(X[B,1024] @ W^T + c)
//   X = [text | image], W/c precomputed from small weights.
//   B = 65536, H = 256, K = 1024.
// Reassociated precompute (depth 2):
//   X1 = Wf1@Wo, X2 = Wf2@Wo          [256x256]
//   Y_t = Wv@W_text, Y_i = Wv@W_img   [256x512]
//   W[:, :512] = X2@Y_t ; W[:, 512:] = X1@Y_i   (fp16)
//   b1 = Wo@bv + bo ; u_t = Wv@b_text ; u_i = Wv@b_img
//   c  = X1@u_i + X2@u_t + (Wf1+Wf2)@b1 + b_fuse
// ============================================================
#define HDIM 256
#define KTOT 1024

// ---------------- device scratch ----------------
__device__ float  g_X1[HDIM * HDIM];
__device__ float  g_X2[HDIM * HDIM];
__device__ float  g_Yt[HDIM * 512];
__device__ float  g_Yi[HDIM * 512];
__device__ __half g_W16[HDIM * KTOT];
__device__ float  g_b1[HDIM];
__device__ float  g_ut[HDIM];
__device__ float  g_ui[HDIM];
__device__ float  g_c[HDIM];

// ---------------- PTX helpers ----------------
__device__ __forceinline__ uint32_t smem_u32(const void* p) {
    uint32_t a;
    asm("{ .reg .u64 t; cvta.to.shared.u64 t, %1; cvt.u32.u64 %0, t; }"
        : "=r"(a) : "l"(p));
    return a;
}

#define SW(x) ((x) ^ (((x) >> 3) & 0x70))

#define LDSM_X4(r0, r1, r2, r3, addr) \
    asm volatile("ldmatrix.sync.aligned.m8n8.x4.shared.b16 {%0,%1,%2,%3}, [%4];\n" \
        : "=r"(r0), "=r"(r1), "=r"(r2), "=r"(r3) : "r"(addr))

#define LDS64(f0, f1, addr) \
    asm volatile("ld.shared.v2.f32 {%0,%1}, [%2];\n" \
        : "=f"(f0), "=f"(f1) : "r"(addr))

#define MMA16816(d, a, b0_, b1_) \
    asm volatile("mma.sync.aligned.m16n8k16.row.col.f32.f16.f16.f32 " \
        "{%0,%1,%2,%3}, {%4,%5,%6,%7}, {%8,%9}, {%0,%1,%2,%3};\n" \
        : "+f"((d)[0]), "+f"((d)[1]), "+f"((d)[2]), "+f"((d)[3]) \
        : "r"((a)[0]), "r"((a)[1]), "r"((a)[2]), "r"((a)[3]), "r"(b0_), "r"(b1_))

#define CP_ASYNC16(dst, src) \
    asm volatile("cp.async.cg.shared.global [%0], [%1], 16;\n" :: "r"(dst), "l"(src))
#define CP_COMMIT() asm volatile("cp.async.commit_group;\n")
#define CP_WAIT0()  asm volatile("cp.async.wait_group 0;\n" ::: "memory")
#define CP_WAIT1()  asm volatile("cp.async.wait_group 1;\n" ::: "memory")

__device__ __forceinline__ uint32_t pkh2(float x, float y) {
    __half2 h = __floats2half2_rn(x, y);
    return *(uint32_t*)&h;
}

// ============================================================
// Precompute: 64x64-tile fp32 GEMM, 4x4/thread, reg-double-buffered
// ============================================================
template<bool HALF_OUT>
__device__ __forceinline__ void gemm64_body(const float* __restrict__ A, int lda,
                                            const float* __restrict__ B, int ldb,
                                            void* __restrict__ C, int ldc, int K,
                                            int i0, int j0) {
    __shared__ float As[32][72];   // As[k][m] (transposed)
    __shared__ float Bs[32][72];   // Bs[k][n]
    const int t = threadIdx.x;
    const int tx = t & 15, ty = t >> 4;
    float acc[4][4] = {};

    int ar[8], ac[8], br[8], bc[8];
    #pragma unroll
    for (int u = 0; u < 8; u++) {
        int idx = t + u * 256;
        ar[u] = idx >> 5;  ac[u] = idx & 31;   // A: 64 rows x 32 k
        br[u] = idx >> 6;  bc[u] = idx & 63;   // B: 32 k x 64 cols
    }
    float ra[8], rb[8];
    #pragma unroll
    for (int u = 0; u < 8; u++) {
        ra[u] = A[(size_t)(i0 + ar[u]) * lda + ac[u]];
        rb[u] = B[(size_t)br[u] * ldb + j0 + bc[u]];
    }

    for (int k0 = 0; k0 < K; k0 += 32) {
        #pragma unroll
        for (int u = 0; u < 8; u++) {
            As[ac[u]][ar[u]] = ra[u];
            Bs[br[u]][bc[u]] = rb[u];
        }
        __syncthreads();
        if (k0 + 32 < K) {
            #pragma unroll
            for (int u = 0; u < 8; u++) {
                ra[u] = A[(size_t)(i0 + ar[u]) * lda + k0 + 32 + ac[u]];
                rb[u] = B[(size_t)(k0 + 32 + br[u]) * ldb + j0 + bc[u]];
            }
        }
        #pragma unroll
        for (int k = 0; k < 32; k++) {
            float4 a4 = *(const float4*)&As[k][ty * 4];
            float4 b4 = *(const float4*)&Bs[k][tx * 4];
            acc[0][0] += a4.x * b4.x; acc[0][1] += a4.x * b4.y;
            acc[0][2] += a4.x * b4.z; acc[0][3] += a4.x * b4.w;
            acc[1][0] += a4.y * b4.x; acc[1][1] += a4.y * b4.y;
            acc[1][2] += a4.y * b4.z; acc[1][3] += a4.y * b4.w;
            acc[2][0] += a4.z * b4.x; acc[2][1] += a4.z * b4.y;
            acc[2][2] += a4.z * b4.z; acc[2][3] += a4.z * b4.w;
            acc[3][0] += a4.w * b4.x; acc[3][1] += a4.w * b4.y;
            acc[3][2] += a4.w * b4.z; acc[3][3] += a4.w * b4.w;
        }
        __syncthreads();
    }
    #pragma unroll
    for (int r = 0; r < 4; r++)
        #pragma unroll
        for (int c = 0; c < 4; c++) {
            size_t o = (size_t)(i0 + ty * 4 + r) * ldc + j0 + tx * 4 + c;
            if (HALF_OUT) ((__half*)C)[o] = __float2half_rn(acc[r][c]);
            else          ((float*)C)[o]  = acc[r][c];
        }
}

__device__ __forceinline__ float dot256(const float* __restrict__ a,
                                        const float* __restrict__ b) {
    const float4* a4 = (const float4*)a;
    const float4* b4 = (const float4*)b;
    float s = 0.f;
    #pragma unroll 8
    for (int k = 0; k < 64; k++) {
        float4 x = __ldg(&a4[k]), y = __ldg(&b4[k]);
        s += x.x * y.x + x.y * y.y + x.z * y.z + x.w * y.w;
    }
    return s;
}

// Launch 1 (input-only work), grid (8,4,4)
__global__ void k_pre1(const float* __restrict__ Wo, const float* __restrict__ Wv,
                       const float* __restrict__ W_fuse,
                       const float* __restrict__ W_text, const float* __restrict__ W_img,
                       const float* __restrict__ in_proj_b,
                       const float* __restrict__ out_proj_b,
                       const float* __restrict__ b_text, const float* __restrict__ b_img) {
    const int z = blockIdx.z;
    if (z == 0) {
        if (blockIdx.x < 4) {
            gemm64_body<false>(W_fuse, 512, Wo, 256, g_X1, 256, 256,
                               blockIdx.y * 64, blockIdx.x * 64);
        } else if (blockIdx.y == 0) {
            const int i = threadIdx.x;
            if (blockIdx.x == 4)
                g_b1[i] = dot256(Wo + i * HDIM, in_proj_b + 2 * HDIM) + out_proj_b[i];
            else if (blockIdx.x == 5)
                g_ut[i] = dot256(Wv + i * HDIM, b_text);
            else if (blockIdx.x == 6)
                g_ui[i] = dot256(Wv + i * HDIM, b_img);
        }
        return;
    }
    if (z == 1) {
        if (blockIdx.x < 4)
            gemm64_body<false>(W_fuse + 256, 512, Wo, 256, g_X2, 256, 256,
                               blockIdx.y * 64, blockIdx.x * 64);
        return;
    }
    if (z == 2) {
        gemm64_body<false>(Wv, 256, W_text, 512, g_Yt, 512, 256,
                           blockIdx.y * 64, blockIdx.x * 64);
        return;
    }
    gemm64_body<false>(Wv, 256, W_img, 512, g_Yi, 512, 256,
                       blockIdx.y * 64, blockIdx.x * 64);
}

// Launch 2, grid (8,4,3)
__global__ void k_pre2(const float* __restrict__ W_fuse,
                       const float* __restrict__ b_fuse) {
    const int z = blockIdx.z;
    if (z == 0) {
        gemm64_body<true>(g_X2, 256, g_Yt, 512, g_W16, 1024, 256,
                          blockIdx.y * 64, blockIdx.x * 64);
        return;
    }
    if (z == 1) {
        gemm64_body<true>(g_X1, 256, g_Yi, 512, g_W16 + 512, 1024, 256,
                          blockIdx.y * 64, blockIdx.x * 64);
        return;
    }
    if (blockIdx.x | blockIdx.y) return;
    const int i = threadIdx.x;
    float s = b_fuse[i] + dot256(g_X1 + i * HDIM, g_ui) + dot256(g_X2 + i * HDIM, g_ut);
    const float4* w1 = (const float4*)(W_fuse + i * 512);
    const float4* w2 = (const float4*)(W_fuse + i * 512 + 256);
    const float4* v1 = (const float4*)g_b1;
    #pragma unroll 8
    for (int k = 0; k < 64; k++) {
        float4 c1 = __ldg(&w1[k]), c2 = __ldg(&w2[k]), b = v1[k];
        s += (c1.x + c2.x) * b.x + (c1.y + c2.y) * b.y
           + (c1.z + c2.z) * b.z + (c1.w + c2.w) * b.w;
    }
    g_c[i] = s;
}

// ============================================================
// Main GEMM: CTA tile 64x128, 256 threads (8 warps, warp 32x32),
// K-chunk 64, THREE smem stages + cp.async.wait_group 1 (loads run
// a full chunk ahead), 2 CTAs/SM.
// A: cp.async fp32, 288B row stride; frags via LDS.64 + cvt.
// B: cp.async fp16 swizzled + LDSM, rolling fragment prefetch.
// Grid: (batch/64) * 2 n-halves = 2048 CTAs (~6.9 waves, ~1% tail).
// ============================================================
#define A_STRIDE 288                       // bytes per A smem row (72 floats)
#define A_BYTES  (64 * A_STRIDE)           // 18432
#define B_BYTES  16384                     // 128 rows x 64 fp16
#define STAGE    (A_BYTES + B_BYTES)       // 34816
#define DYNSMEM  (1024 + 1024 + 3 * STAGE) // 106496

__global__ void __launch_bounds__(256, 2)
fused_gemm(const float* __restrict__ text, const float* __restrict__ image,
           float* __restrict__ out) {
    extern __shared__ char smem_raw[];
    char* dsm = (char*)(((uintptr_t)smem_raw + 1023) & ~(uintptr_t)1023);
    const uint32_t sb = smem_u32(dsm);
    const int tid = threadIdx.x;
    const int lane = tid & 31;
    const int wid = tid >> 5;          // 0..7
    const int wm = wid & 1;            // 2 m-blocks of 32
    const int wn = wid >> 1;           // 4 n-blocks of 32
    const int mblk = blockIdx.x >> 1;
    const int nb   = blockIdx.x & 1;   // which 128-col half of W

    float* bias_s = (float*)dsm;
    if (tid < 128) bias_s[tid] = g_c[nb * 128 + tid];

    const float* srcT = text  + (size_t)mblk * 64 * 512;
    const float* srcI = image + (size_t)mblk * 64 * 512;
    const __half* Wb  = g_W16 + (size_t)nb * 128 * 1024;

    const int a_c16 = tid & 15, a_r0 = tid >> 4;  // A: rows a_r0 + u*16, u<4
    const int b_c16 = tid & 7,  b_r0 = tid >> 3;  // B: rows b_r0 + u*32, u<4

    // -------- prologue: stages 0 and 1 --------
    #pragma unroll
    for (int p = 0; p < 2; p++) {
        const float* src = srcT;          // chunks 0,1 are text
        const int kl = p * 64;
        uint32_t As_ = sb + 2048 + p * STAGE;
        #pragma unroll
        for (int u = 0; u < 4; u++) {
            int r = a_r0 + u * 16;
            CP_ASYNC16(As_ + (uint32_t)(r * A_STRIDE + a_c16 * 16),
                       src + (size_t)r * 512 + kl + a_c16 * 4);
        }
        uint32_t Bb = As_ + A_BYTES;
        #pragma unroll
        for (int u = 0; u < 4; u++) {
            int r = b_r0 + u * 32;
            uint32_t dst = Bb + SW((uint32_t)(r * 128 + b_c16 * 16));
            CP_ASYNC16(dst, Wb + (size_t)r * 1024 + p * 64 + b_c16 * 8);
        }
        CP_COMMIT();
    }

    float acc[2][4][4] = {};

    const uint32_t xorv  = (uint32_t)((lane & 7) << 4);
    const int      rl    = lane & 15;
    const uint32_t khalf = (uint32_t)(((lane >> 4) & 1) * 16);
    const int      g     = lane >> 2;
    const int      c2    = (lane & 3) * 2;

    #pragma unroll 1
    for (int kc = 0; kc < 16; kc++) {
        // stage kc is complete once at most 1 newer group is outstanding
        if (kc == 15) { CP_WAIT0(); } else { CP_WAIT1(); }
        __syncthreads();

        // ---- issue stage kc+2 (overwrites stage consumed at kc-1) ----
        if (kc + 2 <= 15) {
            const int kn = kc + 2;
            const float* src = (kn < 8) ? srcT : srcI;
            const int kl = (kn & 7) * 64;
            uint32_t As_ = sb + 2048 + (uint32_t)((kn % 3) * STAGE);
            #pragma unroll
            for (int u = 0; u < 4; u++) {
                int r = a_r0 + u * 16;
                CP_ASYNC16(As_ + (uint32_t)(r * A_STRIDE + a_c16 * 16),
                           src + (size_t)r * 512 + kl + a_c16 * 4);
            }
            uint32_t Bb = As_ + A_BYTES;
            #pragma unroll
            for (int u = 0; u < 4; u++) {
                int r = b_r0 + u * 32;
                uint32_t dst = Bb + SW((uint32_t)(r * 128 + b_c16 * 16));
                CP_ASYNC16(dst, Wb + (size_t)r * 1024 + kn * 64 + b_c16 * 8);
            }
            CP_COMMIT();
        }

        // ---- compute on stage kc%3 ----
        const uint32_t Ab = sb + 2048 + (uint32_t)((kc % 3) * STAGE);
        const uint32_t Bb = Ab + A_BYTES;
        uint32_t bf[2][4];
        {   // preload B group 0 (ks=0, n-group 0)
            uint32_t addr = (Bb + (uint32_t)((wn * 32 + rl) * 128) + khalf) ^ xorv;
            LDSM_X4(bf[0][0], bf[0][1], bf[0][2], bf[0][3], addr);
        }
        #pragma unroll
        for (int ks = 0; ks < 4; ks++) {
            // A fragments from fp32 smem (LDS.64 + cvt)
            uint32_t af[2][4];
            #pragma unroll
            for (int im = 0; im < 2; im++) {
                uint32_t base = Ab + (uint32_t)((wm * 32 + im * 16 + g) * A_STRIDE
                                                + (ks * 16 + c2) * 4);
                float x0, x1, y0, y1, z0, z1, w0, w1;
                LDS64(x0, x1, base);
                LDS64(y0, y1, base + 8 * A_STRIDE);
                LDS64(z0, z1, base + 32);
                LDS64(w0, w1, base + 8 * A_STRIDE + 32);
                af[im][0] = pkh2(x0, x1);
                af[im][1] = pkh2(y0, y1);
                af[im][2] = pkh2(z0, z1);
                af[im][3] = pkh2(w0, w1);
            }
            #pragma unroll
            for (int grp = 0; grp < 2; grp++) {
                const int bc = (2 * ks + grp) & 1, bn = bc ^ 1;
                // rolling B prefetch: next group (possibly next ks, group 0)
                if (ks < 3 || grp < 1) {
                    const int ngrp = grp ^ 1;
                    const int nks = ks + grp;    // grp==1 -> next ks
                    uint32_t addr = (Bb + (uint32_t)((wn * 32 + ngrp * 16 + rl) * 128)
                                        + (uint32_t)(nks * 32) + khalf) ^ xorv;
                    LDSM_X4(bf[bn][0], bf[bn][1], bf[bn][2], bf[bn][3], addr);
                }
                #pragma unroll
                for (int im = 0; im < 2; im++) {
                    MMA16816(acc[im][2 * grp],     af[im], bf[bc][0], bf[bc][2]);
                    MMA16816(acc[im][2 * grp + 1], af[im], bf[bc][1], bf[bc][3]);
                }
            }
        }
        __syncthreads();
    }

    // -------- epilogue: + bias, relu, store --------
    const int cpair = (lane & 3) * 2;
    #pragma unroll
    for (int im = 0; im < 2; im++) {
        int m0 = mblk * 64 + wm * 32 + im * 16 + g;
        #pragma unroll
        for (int j = 0; j < 4; j++) {
            int nl = wn * 32 + j * 8 + cpair;          // local col 0..127
            int n  = nb * 128 + nl;                    // global col
            float bv0 = bias_s[nl], bv1 = bias_s[nl + 1];
            float2 v0 = make_float2(fmaxf(acc[im][j][0] + bv0, 0.f),
                                    fmaxf(acc[im][j][1] + bv1, 0.f));
            float2 v1 = make_float2(fmaxf(acc[im][j][2] + bv0, 0.f),
                                    fmaxf(acc[im][j][3] + bv1, 0.f));
            *(float2*)(out + (size_t)m0 * 256 + n)       = v0;
            *(float2*)(out + (size_t)(m0 + 8) * 256 + n) = v1;
        }
    }
}

// ============================================================
// kernel_launch
// ============================================================
extern "C" void kernel_launch(void* const* d_in, const int* in_sizes, int n_in,
                              void* d_out, int out_size) {
    const float* text       = (const float*)d_in[0];
    const float* image      = (const float*)d_in[1];
    const float* W_text     = (const float*)d_in[2];
    const float* b_text     = (const float*)d_in[3];
    const float* W_img      = (const float*)d_in[4];
    const float* b_img      = (const float*)d_in[5];
    const float* in_proj_w  = (const float*)d_in[6];
    const float* in_proj_b  = (const float*)d_in[7];
    const float* out_proj_w = (const float*)d_in[8];
    const float* out_proj_b = (const float*)d_in[9];
    const float* W_fuse     = (const float*)d_in[10];
    const float* b_fuse     = (const float*)d_in[11];
    const int batch = in_sizes[0] / 512;

    k_pre1<<<dim3(8, 4, 4), 256>>>(out_proj_w, in_proj_w + 512 * 256, W_fuse,
                                   W_text, W_img, in_proj_b, out_proj_b,
                                   b_text, b_img);
    k_pre2<<<dim3(8, 4, 3), 256>>>(W_fuse, b_fuse);

    cudaFuncSetAttribute(fused_gemm, cudaFuncAttributeMaxDynamicSharedMemorySize, DYNSMEM);
    fused_gemm<<<(batch / 64) * 2, 256, DYNSMEM>>>(text, image, (float*)d_out);
}

// round 12
// speedup vs baseline: 1.2052x; 1.2052x over previous
#include <cuda_runtime.h>
#include <cuda_fp16.h>
#include <cstdint>

// ============================================================
// Problem: out[B,256] = relu(X[B,1024] @ W^T + c)
//   X = [text | image], W/c precomputed from small weights.
//   B = 65536, H = 256, K = 1024.
// Reassociated precompute (depth 2):
//   X1 = Wf1@Wo, X2 = Wf2@Wo          [256x256]
//   Y_t = Wv@W_text, Y_i = Wv@W_img   [256x512]
//   W[:, :512] = X2@Y_t ; W[:, 512:] = X1@Y_i   (fp16)
//   b1 = Wo@bv + bo ; u_t = Wv@b_text ; u_i = Wv@b_img
//   c  = X1@u_i + X2@u_t + (Wf1+Wf2)@b1 + b_fuse
// ============================================================
#define HDIM 256
#define KTOT 1024

// ---------------- device scratch ----------------
__device__ float  g_X1[HDIM * HDIM];
__device__ float  g_X2[HDIM * HDIM];
__device__ float  g_Yt[HDIM * 512];
__device__ float  g_Yi[HDIM * 512];
__device__ __half g_W16[HDIM * KTOT];
__device__ float  g_b1[HDIM];
__device__ float  g_ut[HDIM];
__device__ float  g_ui[HDIM];
__device__ float  g_c[HDIM];

// ---------------- PTX helpers ----------------
__device__ __forceinline__ uint32_t smem_u32(const void* p) {
    uint32_t a;
    asm("{ .reg .u64 t; cvta.to.shared.u64 t, %1; cvt.u32.u64 %0, t; }"
        : "=r"(a) : "l"(p));
    return a;
}

#define SW(x) ((x) ^ (((x) >> 3) & 0x70))

#define LDSM_X4(r0, r1, r2, r3, addr) \
    asm volatile("ldmatrix.sync.aligned.m8n8.x4.shared.b16 {%0,%1,%2,%3}, [%4];\n" \
        : "=r"(r0), "=r"(r1), "=r"(r2), "=r"(r3) : "r"(addr))

#define MMA16816(d, a, b0_, b1_) \
    asm volatile("mma.sync.aligned.m16n8k16.row.col.f32.f16.f16.f32 " \
        "{%0,%1,%2,%3}, {%4,%5,%6,%7}, {%8,%9}, {%0,%1,%2,%3};\n" \
        : "+f"((d)[0]), "+f"((d)[1]), "+f"((d)[2]), "+f"((d)[3]) \
        : "r"((a)[0]), "r"((a)[1]), "r"((a)[2]), "r"((a)[3]), "r"(b0_), "r"(b1_))

#define CP_ASYNC16(dst, src) \
    asm volatile("cp.async.cg.shared.global [%0], [%1], 16;\n" :: "r"(dst), "l"(src))
#define CP_COMMIT() asm volatile("cp.async.commit_group;\n")
#define CP_WAIT0()  asm volatile("cp.async.wait_group 0;\n" ::: "memory")

// ============================================================
// Precompute: 64x64-tile fp32 GEMM, 512 threads, intra-CTA split-K
// (each 256-thread half does half the K chunks; smem reduction).
// ============================================================
template<bool HALF_OUT>
__device__ __forceinline__ void gemm64_body2(const float* __restrict__ A, int lda,
                                             const float* __restrict__ B, int ldb,
                                             void* __restrict__ C, int ldc, int K,
                                             int i0, int j0) {
    __shared__ float As[2][32][72];
    __shared__ float Bs[2][32][72];
    const int t  = threadIdx.x;        // 0..511
    const int h  = t >> 8;             // K-half (0 or 1)
    const int lt = t & 255;
    const int tx = lt & 15, ty = lt >> 4;
    const int khalf = K >> 1;
    const int kbase = h * khalf;
    float acc[4][4] = {};

    int ar[8], ac[8], br[8], bc[8];
    #pragma unroll
    for (int u = 0; u < 8; u++) {
        int idx = lt + u * 256;
        ar[u] = idx >> 5;  ac[u] = idx & 31;   // A: 64 rows x 32 k
        br[u] = idx >> 6;  bc[u] = idx & 63;   // B: 32 k x 64 cols
    }
    float ra[8], rb[8];
    #pragma unroll
    for (int u = 0; u < 8; u++) {
        ra[u] = A[(size_t)(i0 + ar[u]) * lda + kbase + ac[u]];
        rb[u] = B[(size_t)(kbase + br[u]) * ldb + j0 + bc[u]];
    }

    for (int k0 = kbase; k0 < kbase + khalf; k0 += 32) {
        #pragma unroll
        for (int u = 0; u < 8; u++) {
            As[h][ac[u]][ar[u]] = ra[u];
            Bs[h][br[u]][bc[u]] = rb[u];
        }
        __syncthreads();
        if (k0 + 32 < kbase + khalf) {
            #pragma unroll
            for (int u = 0; u < 8; u++) {
                ra[u] = A[(size_t)(i0 + ar[u]) * lda + k0 + 32 + ac[u]];
                rb[u] = B[(size_t)(k0 + 32 + br[u]) * ldb + j0 + bc[u]];
            }
        }
        #pragma unroll
        for (int k = 0; k < 32; k++) {
            float4 a4 = *(const float4*)&As[h][k][ty * 4];
            float4 b4 = *(const float4*)&Bs[h][k][tx * 4];
            acc[0][0] += a4.x * b4.x; acc[0][1] += a4.x * b4.y;
            acc[0][2] += a4.x * b4.z; acc[0][3] += a4.x * b4.w;
            acc[1][0] += a4.y * b4.x; acc[1][1] += a4.y * b4.y;
            acc[1][2] += a4.y * b4.z; acc[1][3] += a4.y * b4.w;
            acc[2][0] += a4.z * b4.x; acc[2][1] += a4.z * b4.y;
            acc[2][2] += a4.z * b4.z; acc[2][3] += a4.z * b4.w;
            acc[3][0] += a4.w * b4.x; acc[3][1] += a4.w * b4.y;
            acc[3][2] += a4.w * b4.z; acc[3][3] += a4.w * b4.w;
        }
        __syncthreads();
    }

    // ---- reduce half 1 into half 0 via smem (reuse As/Bs space) ----
    float* red = &As[0][0][0];         // 16 x 257 floats fits in As
    if (h == 1) {
        #pragma unroll
        for (int i = 0; i < 16; i++)
            red[i * 257 + lt] = acc[i >> 2][i & 3];
    }
    __syncthreads();
    if (h == 0) {
        #pragma unroll
        for (int i = 0; i < 16; i++)
            acc[i >> 2][i & 3] += red[i * 257 + lt];
        #pragma unroll
        for (int r = 0; r < 4; r++)
            #pragma unroll
            for (int c = 0; c < 4; c++) {
                size_t o = (size_t)(i0 + ty * 4 + r) * ldc + j0 + tx * 4 + c;
                if (HALF_OUT) ((__half*)C)[o] = __float2half_rn(acc[r][c]);
                else          ((float*)C)[o]  = acc[r][c];
            }
    }
}

__device__ __forceinline__ float dot256(const float* __restrict__ a,
                                        const float* __restrict__ b) {
    const float4* a4 = (const float4*)a;
    const float4* b4 = (const float4*)b;
    float s = 0.f;
    #pragma unroll 8
    for (int k = 0; k < 64; k++) {
        float4 x = __ldg(&a4[k]), y = __ldg(&b4[k]);
        s += x.x * y.x + x.y * y.y + x.z * y.z + x.w * y.w;
    }
    return s;
}

// Launch 1 (input-only work), grid (8,4,4), 512 threads
__global__ void __launch_bounds__(512, 1)
k_pre1(const float* __restrict__ Wo, const float* __restrict__ Wv,
       const float* __restrict__ W_fuse,
       const float* __restrict__ W_text, const float* __restrict__ W_img,
       const float* __restrict__ in_proj_b,
       const float* __restrict__ out_proj_b,
       const float* __restrict__ b_text, const float* __restrict__ b_img) {
    const int z = blockIdx.z;
    if (z == 0) {
        if (blockIdx.x < 4) {
            gemm64_body2<false>(W_fuse, 512, Wo, 256, g_X1, 256, 256,
                                blockIdx.y * 64, blockIdx.x * 64);
        } else if (blockIdx.y == 0 && threadIdx.x < 256) {
            const int i = threadIdx.x;
            if (blockIdx.x == 4)
                g_b1[i] = dot256(Wo + i * HDIM, in_proj_b + 2 * HDIM) + out_proj_b[i];
            else if (blockIdx.x == 5)
                g_ut[i] = dot256(Wv + i * HDIM, b_text);
            else if (blockIdx.x == 6)
                g_ui[i] = dot256(Wv + i * HDIM, b_img);
        }
        return;
    }
    if (z == 1) {
        if (blockIdx.x < 4)
            gemm64_body2<false>(W_fuse + 256, 512, Wo, 256, g_X2, 256, 256,
                                blockIdx.y * 64, blockIdx.x * 64);
        return;
    }
    if (z == 2) {
        gemm64_body2<false>(Wv, 256, W_text, 512, g_Yt, 512, 256,
                            blockIdx.y * 64, blockIdx.x * 64);
        return;
    }
    gemm64_body2<false>(Wv, 256, W_img, 512, g_Yi, 512, 256,
                        blockIdx.y * 64, blockIdx.x * 64);
}

// Launch 2, grid (8,4,3), 512 threads
__global__ void __launch_bounds__(512, 1)
k_pre2(const float* __restrict__ W_fuse, const float* __restrict__ b_fuse) {
    const int z = blockIdx.z;
    if (z == 0) {
        gemm64_body2<true>(g_X2, 256, g_Yt, 512, g_W16, 1024, 256,
                           blockIdx.y * 64, blockIdx.x * 64);
        return;
    }
    if (z == 1) {
        gemm64_body2<true>(g_X1, 256, g_Yi, 512, g_W16 + 512, 1024, 256,
                           blockIdx.y * 64, blockIdx.x * 64);
        return;
    }
    if (blockIdx.x | blockIdx.y) return;
    if (threadIdx.x >= 256) return;
    const int i = threadIdx.x;
    float s = b_fuse[i] + dot256(g_X1 + i * HDIM, g_ui) + dot256(g_X2 + i * HDIM, g_ut);
    const float4* w1 = (const float4*)(W_fuse + i * 512);
    const float4* w2 = (const float4*)(W_fuse + i * 512 + 256);
    const float4* v1 = (const float4*)g_b1;
    #pragma unroll 8
    for (int k = 0; k < 64; k++) {
        float4 c1 = __ldg(&w1[k]), c2 = __ldg(&w2[k]), b = v1[k];
        s += (c1.x + c2.x) * b.x + (c1.y + c2.y) * b.y
           + (c1.z + c2.z) * b.z + (c1.w + c2.w) * b.w;
    }
    g_c[i] = s;
}

// ============================================================
// Main GEMM (EXACT round-9 structure, best measured):
// CTA tile 64x256, 256 threads (8 warps, warp 32x64), K-chunk 64,
// double-buffered smem, 2 CTAs/SM, reg-prefetched A, cp.async B,
// constant-index fragment pipelining.
// ============================================================
#define STAGE 40960                    // 8KB A + 32KB B
#define DYNSMEM (1024 + 1024 + 2 * STAGE)

__global__ void __launch_bounds__(256, 2)
fused_gemm(const float* __restrict__ text, const float* __restrict__ image,
           float* __restrict__ out) {
    extern __shared__ char smem_raw[];
    char* dsm = (char*)(((uintptr_t)smem_raw + 1023) & ~(uintptr_t)1023);
    const uint32_t sb = smem_u32(dsm);
    const int tid = threadIdx.x;
    const int lane = tid & 31;
    const int wid = tid >> 5;          // 0..7
    const int wm = wid & 1;            // 2 m-blocks of 32
    const int wn = wid >> 1;           // 4 n-blocks of 64
    const int mblk = blockIdx.x;

    float* bias_s = (float*)dsm;
    bias_s[tid] = g_c[tid];

    const float* srcT = text  + (size_t)mblk * 64 * 512;
    const float* srcI = image + (size_t)mblk * 64 * 512;

    const int a_c4 = tid & 15, a_r0 = tid >> 4;   // A: rows a_r0 + u*16, u<4
    const int b_c16 = tid & 7, b_r0 = tid >> 3;   // B: rows b_r0 + u*32, u<8

    // -------- prologue: chunk 0 --------
    float4 fa[4];
    #pragma unroll
    for (int u = 0; u < 4; u++)
        fa[u] = __ldg((const float4*)(srcT + (size_t)(a_r0 + u * 16) * 512 + a_c4 * 4));
    {
        uint32_t Bb = sb + 1024 + 8192;
        #pragma unroll
        for (int u = 0; u < 8; u++) {
            int r = b_r0 + u * 32;
            uint32_t dst = Bb + SW((uint32_t)(r * 128 + b_c16 * 16));
            CP_ASYNC16(dst, g_W16 + (size_t)r * 1024 + b_c16 * 8);
        }
        CP_COMMIT();
    }
    {
        char* Ab = dsm + 1024;
        #pragma unroll
        for (int u = 0; u < 4; u++) {
            int r = a_r0 + u * 16;
            uint32_t off = SW((uint32_t)(r * 128 + a_c4 * 8));
            __half2 h0 = __floats2half2_rn(fa[u].x, fa[u].y);
            __half2 h1 = __floats2half2_rn(fa[u].z, fa[u].w);
            *(uint2*)(Ab + off) = make_uint2(*(uint32_t*)&h0, *(uint32_t*)&h1);
        }
    }
    CP_WAIT0();
    __syncthreads();

    float acc[2][8][4] = {};

    const uint32_t xorv  = (uint32_t)((lane & 7) << 4);
    const int      rl    = lane & 15;
    const uint32_t khalf = (uint32_t)(((lane >> 4) & 1) * 16);

    #pragma unroll 1
    for (int kc = 0; kc < 16; kc++) {
        const int cur = kc & 1;
        const int nxt = cur ^ 1;

        // ---- prefetch next chunk: A -> regs, B -> cp.async ----
        if (kc < 15) {
            const int kn = kc + 1;
            const float* src = (kn < 8) ? srcT : srcI;
            const int kl = (kn & 7) * 64;
            #pragma unroll
            for (int u = 0; u < 4; u++)
                fa[u] = __ldg((const float4*)(src + (size_t)(a_r0 + u * 16) * 512 + kl + a_c4 * 4));
            uint32_t Bb = sb + 1024 + nxt * STAGE + 8192;
            #pragma unroll
            for (int u = 0; u < 8; u++) {
                int r = b_r0 + u * 32;
                uint32_t dst = Bb + SW((uint32_t)(r * 128 + b_c16 * 16));
                CP_ASYNC16(dst, g_W16 + (size_t)r * 1024 + kn * 64 + b_c16 * 8);
            }
            CP_COMMIT();
        }

        // ---- compute on cur, fragment-pipelined ----
        const uint32_t Ab = sb + 1024 + cur * STAGE;
        const uint32_t Bb = Ab + 8192;
        uint32_t af[2][2][4];   // [ks&1][im][reg]
        uint32_t bf[2][4];      // [group&1][reg]

        // preload ks=0: A frags (both im) + B group 0
        #pragma unroll
        for (int im = 0; im < 2; im++) {
            uint32_t addr = (Ab + (uint32_t)((wm * 32 + im * 16 + rl) * 128) + khalf) ^ xorv;
            LDSM_X4(af[0][im][0], af[0][im][1], af[0][im][2], af[0][im][3], addr);
        }
        {
            uint32_t addr = (Bb + (uint32_t)((wn * 64 + rl) * 128) + khalf) ^ xorv;
            LDSM_X4(bf[0][0], bf[0][1], bf[0][2], bf[0][3], addr);
        }

        #pragma unroll
        for (int ks = 0; ks < 4; ks++) {
            const int cb = ks & 1;
            #pragma unroll
            for (int in_ = 0; in_ < 4; in_++) {
                const int bc = in_ & 1, bn = bc ^ 1;
                if (in_ < 3) {
                    // prefetch next B group within this ks
                    uint32_t addr = (Bb + (uint32_t)((wn * 64 + (in_ + 1) * 16 + rl) * 128)
                                        + (uint32_t)(ks * 32) + khalf) ^ xorv;
                    LDSM_X4(bf[bn][0], bf[bn][1], bf[bn][2], bf[bn][3], addr);
                } else if (ks < 3) {
                    // prefetch next ks: A frags + B group 0
                    #pragma unroll
                    for (int im = 0; im < 2; im++) {
                        uint32_t addr = (Ab + (uint32_t)((wm * 32 + im * 16 + rl) * 128)
                                            + (uint32_t)((ks + 1) * 32) + khalf) ^ xorv;
                        LDSM_X4(af[cb ^ 1][im][0], af[cb ^ 1][im][1],
                                af[cb ^ 1][im][2], af[cb ^ 1][im][3], addr);
                    }
                    uint32_t addr = (Bb + (uint32_t)((wn * 64 + rl) * 128)
                                        + (uint32_t)((ks + 1) * 32) + khalf) ^ xorv;
                    LDSM_X4(bf[bn][0], bf[bn][1], bf[bn][2], bf[bn][3], addr);
                }
                #pragma unroll
                for (int im = 0; im < 2; im++) {
                    MMA16816(acc[im][2 * in_],     af[cb][im], bf[bc][0], bf[bc][2]);
                    MMA16816(acc[im][2 * in_ + 1], af[cb][im], bf[bc][1], bf[bc][3]);
                }
            }
        }

        // ---- stage A-next into smem, then close the stage ----
        if (kc < 15) {
            char* Abn = dsm + 1024 + nxt * STAGE;
            #pragma unroll
            for (int u = 0; u < 4; u++) {
                int r = a_r0 + u * 16;
                uint32_t off = SW((uint32_t)(r * 128 + a_c4 * 8));
                __half2 h0 = __floats2half2_rn(fa[u].x, fa[u].y);
                __half2 h1 = __floats2half2_rn(fa[u].z, fa[u].w);
                *(uint2*)(Abn + off) = make_uint2(*(uint32_t*)&h0, *(uint32_t*)&h1);
            }
            CP_WAIT0();
        }
        __syncthreads();
    }

    // -------- epilogue: + bias, relu, store --------
    const int g = lane >> 2;
    const int cpair = (lane & 3) * 2;
    #pragma unroll
    for (int im = 0; im < 2; im++) {
        int m0 = mblk * 64 + wm * 32 + im * 16 + g;
        #pragma unroll
        for (int j = 0; j < 8; j++) {
            int n = wn * 64 + j * 8 + cpair;
            float bv0 = bias_s[n], bv1 = bias_s[n + 1];
            float2 v0 = make_float2(fmaxf(acc[im][j][0] + bv0, 0.f),
                                    fmaxf(acc[im][j][1] + bv1, 0.f));
            float2 v1 = make_float2(fmaxf(acc[im][j][2] + bv0, 0.f),
                                    fmaxf(acc[im][j][3] + bv1, 0.f));
            *(float2*)(out + (size_t)m0 * 256 + n)       = v0;
            *(float2*)(out + (size_t)(m0 + 8) * 256 + n) = v1;
        }
    }
}

// ============================================================
// kernel_launch
// ============================================================
extern "C" void kernel_launch(void* const* d_in, const int* in_sizes, int n_in,
                              void* d_out, int out_size) {
    const float* text       = (const float*)d_in[0];
    const float* image      = (const float*)d_in[1];
    const float* W_text     = (const float*)d_in[2];
    const float* b_text     = (const float*)d_in[3];
    const float* W_img      = (const float*)d_in[4];
    const float* b_img      = (const float*)d_in[5];
    const float* in_proj_w  = (const float*)d_in[6];
    const float* in_proj_b  = (const float*)d_in[7];
    const float* out_proj_w = (const float*)d_in[8];
    const float* out_proj_b = (const float*)d_in[9];
    const float* W_fuse     = (const float*)d_in[10];
    const float* b_fuse     = (const float*)d_in[11];
    const int batch = in_sizes[0] / 512;

    k_pre1<<<dim3(8, 4, 4), 512>>>(out_proj_w, in_proj_w + 512 * 256, W_fuse,
                                   W_text, W_img, in_proj_b, out_proj_b,
                                   b_text, b_img);
    k_pre2<<<dim3(8, 4, 3), 512>>>(W_fuse, b_fuse);

    cudaFuncSetAttribute(fused_gemm, cudaFuncAttributeMaxDynamicSharedMemorySize, DYNSMEM);
    fused_gemm<<<batch / 64, 256, DYNSMEM>>>(text, image, (float*)d_out);
}